// round 12
// baseline (speedup 1.0000x reference)
#include <cuda_runtime.h>
#include <cstdint>

// PNN_62156766707845 — GB300 sm_103a, round 12
// R11 + 4-deep A-buffer ring, stage at distance +2, barrier every 2 iters.
// Pipeline: Xi@i+4, emb@i+3, cvt+store@i+2, compute@i.

#define FDIM   39
#define EDIM   16
#define VDIM   100000
#define MTILE  64
#define NTHR   256
#define NCHUNK 10
#define FPC    4
#define NBUF   4

#define RSU     40                   // A row stride in u32 (160B)
#define PLANE_U (64 * RSU)           // 2560
#define BUF_U   (2 * PLANE_U)        // Ah+Al = 5120 u32 = 20KB
#define SMEM_BYTES (NBUF * BUF_U * 4)   // 80KB
#define XS_S    66

// B fragments: [plane][chunk][ktg][ngroup][lane] as uint2
__device__ uint2 Bfrag[2][NCHUNK][FPC][8][32];

__device__ __forceinline__ uint32_t packbf(float lo, float hi) {
    uint32_t r;
    asm("cvt.rn.bf16x2.f32 %0, %1, %2;" : "=r"(r) : "f"(hi), "f"(lo));
    return r;
}
__device__ __forceinline__ float f_lo(uint32_t u) { return __uint_as_float(u << 16); }
__device__ __forceinline__ float f_hi(uint32_t u) { return __uint_as_float(u & 0xFFFF0000u); }

__device__ __forceinline__ void mma16(float* c, const uint32_t* a, const uint32_t* b) {
    asm volatile(
        "mma.sync.aligned.m16n8k16.row.col.f32.bf16.bf16.f32 "
        "{%0,%1,%2,%3}, {%4,%5,%6,%7}, {%8,%9}, {%0,%1,%2,%3};"
        : "+f"(c[0]), "+f"(c[1]), "+f"(c[2]), "+f"(c[3])
        : "r"(a[0]), "r"(a[1]), "r"(a[2]), "r"(a[3]), "r"(b[0]), "r"(b[1]));
}

__device__ __forceinline__ void cvt4_store(uint32_t* hrow, uint32_t* lrow,
                                           float x0, float x1, float x2, float x3,
                                           int posA) {
    uint32_t h0 = packbf(x0, x1);
    uint32_t h1 = packbf(x2, x3);
    uint32_t l0 = packbf(x0 - f_lo(h0), x1 - f_hi(h0));
    uint32_t l1 = packbf(x2 - f_lo(h1), x3 - f_hi(h1));
    hrow[posA] = h0; hrow[posA + 2] = h1;
    lrow[posA] = l0; lrow[posA + 2] = l1;
}

// ---- B prep kernel ----
extern "C" __global__ void prep_b_kernel(const float* __restrict__ w_first,
                                         const float* __restrict__ w_inner)
{
    int t = blockIdx.x * blockDim.x + threadIdx.x;
    if (t >= NCHUNK * FPC * 8 * 32) return;
    const int lane = t & 31;
    const int qr = lane >> 2, qc = lane & 3;
    const int ng  = (t >> 5) & 7;
    const int ktg = (t >> 8) & 3;
    const int c   = t >> 10;
    const int n = ng * 8 + qr;
    const int f = c * FPC + ktg;
    float v0 = 0.f, v1 = 0.f, v2 = 0.f, v3 = 0.f;
    if (f < FDIM) {
        const float* src = (n < 32)
            ? (w_first + ((long long)n * FDIM + f) * EDIM)
            : (w_inner + ((long long)(n - 32) * FDIM + f) * EDIM);
        v0 = src[2 * qc];     v1 = src[2 * qc + 1];
        v2 = src[2 * qc + 8]; v3 = src[2 * qc + 9];
    }
    uint32_t h0 = packbf(v0, v1), h1 = packbf(v2, v3);
    uint32_t l0 = packbf(v0 - f_lo(h0), v1 - f_hi(h0));
    uint32_t l1 = packbf(v2 - f_lo(h1), v3 - f_hi(h1));
    Bfrag[0][c][ktg][ng][lane] = make_uint2(h0, h1);
    Bfrag[1][c][ktg][ng][lane] = make_uint2(l0, l1);
}

extern "C" __global__ void __launch_bounds__(NTHR, 2)
pnn_kernel(const int* __restrict__ Xi, const float* __restrict__ Xv,
           const float* __restrict__ emb,
           const float* __restrict__ lin1W, const float* __restrict__ lin1b,
           const float* __restrict__ lin2W, const float* __restrict__ lin2b,
           const float* __restrict__ lastW, const float* __restrict__ lastb,
           float* __restrict__ out, int B)
{
    extern __shared__ float sm[];
    uint32_t* smu = (uint32_t*)sm;

    const int tid  = threadIdx.x;
    const int wid  = tid >> 5;
    const int lane = tid & 31;
    const int qr   = lane >> 2;
    const int qc   = lane & 3;
    const int tq   = wid & 3;
    const int kh   = wid >> 2;
    const int RM   = (tq & 1) * 32;
    const int CN   = (tq >> 1) * 32;
    const int NG0  = CN >> 3;

    // A staging role
    const int row  = tid >> 2;
    const int q    = tid & 3;
    const int posA = (q < 2) ? 4 * q : 4 * q - 7;
    const int grow = blockIdx.x * MTILE + row;
    const long long rowbase = (long long)((grow < B) ? grow : 0) * FDIM;

    float pf[FPC][4]; float pxv[FPC];
    int   xi[FPC];    float xvr[FPC];

    // ---- prologue: stage chunks 0,1; emb chunk 2 -> pf; Xi chunk 3 -> xi ----
#pragma unroll
    for (int s = 0; s < FPC; s++) {
        // chunk 0 -> buf 0
        int idx = Xi[rowbase + s];
        float xv = Xv[rowbase + s];
        float4 v = *((const float4*)emb + ((long long)s * VDIM + idx) * 4 + q);
        uint32_t* hp = smu + row * RSU + s * 8;
        cvt4_store(hp, hp + PLANE_U, v.x * xv, v.y * xv, v.z * xv, v.w * xv, posA);
        // chunk 1 -> buf 1
        const int f1 = FPC + s;
        idx = Xi[rowbase + f1];
        xv  = Xv[rowbase + f1];
        v = *((const float4*)emb + ((long long)f1 * VDIM + idx) * 4 + q);
        hp = smu + BUF_U + row * RSU + s * 8;
        cvt4_store(hp, hp + PLANE_U, v.x * xv, v.y * xv, v.z * xv, v.w * xv, posA);
        // chunk 2 -> pf
        const int f2 = 2 * FPC + s;
        idx = Xi[rowbase + f2];
        pxv[s] = Xv[rowbase + f2];
        v = *((const float4*)emb + ((long long)f2 * VDIM + idx) * 4 + q);
        pf[s][0] = v.x; pf[s][1] = v.y; pf[s][2] = v.z; pf[s][3] = v.w;
        // chunk 3 indices -> xi
        const int f3 = 3 * FPC + s;
        xi[s]  = Xi[rowbase + f3];
        xvr[s] = Xv[rowbase + f3];
    }
    __syncthreads();

    float acc[2][4][4];
#pragma unroll
    for (int mt = 0; mt < 2; mt++)
#pragma unroll
        for (int nt = 0; nt < 4; nt++)
#pragma unroll
            for (int c = 0; c < 4; c++) acc[mt][nt][c] = 0.f;

    for (int i = 0; i < NCHUNK; i++) {
        // 0) B fragment LDGs for chunk i (L2-resident)
        uint2 bhf[2][4], blf[2][4];
#pragma unroll
        for (int kt = 0; kt < 2; kt++) {
            const int ktg = 2 * kh + kt;
#pragma unroll
            for (int nt = 0; nt < 4; nt++) {
                bhf[kt][nt] = Bfrag[0][i][ktg][NG0 + nt][lane];
                blf[kt][nt] = Bfrag[1][i][ktg][NG0 + nt][lane];
            }
        }
        // 1) cvt+store chunk i+2 from pf into buf (i+2)%NBUF
        if (i + 2 < NCHUNK) {
            uint32_t* base = smu + ((i + 2) & (NBUF - 1)) * BUF_U;
#pragma unroll
            for (int s = 0; s < FPC; s++) {
                uint32_t* hp = base + row * RSU + s * 8;
                cvt4_store(hp, hp + PLANE_U,
                           pf[s][0] * pxv[s], pf[s][1] * pxv[s],
                           pf[s][2] * pxv[s], pf[s][3] * pxv[s], posA);
            }
        }
        // 2) emb LDG chunk i+3 using resident indices
        if (i + 3 < NCHUNK) {
#pragma unroll
            for (int s = 0; s < FPC; s++) {
                const int f = FPC * (i + 3) + s;
                if (f < FDIM) {
                    pxv[s] = xvr[s];
                    float4 v = *((const float4*)emb + ((long long)f * VDIM + xi[s]) * 4 + q);
                    pf[s][0] = v.x; pf[s][1] = v.y; pf[s][2] = v.z; pf[s][3] = v.w;
                } else {
                    pxv[s] = 0.f;
                    pf[s][0] = pf[s][1] = pf[s][2] = pf[s][3] = 0.f;
                }
            }
        }
        // 3) Xi/Xv chunk i+4
        if (i + 4 < NCHUNK) {
#pragma unroll
            for (int s = 0; s < FPC; s++) {
                const int f = FPC * (i + 4) + s;
                if (f < FDIM) {
                    xi[s]  = Xi[rowbase + f];
                    xvr[s] = Xv[rowbase + f];
                } else { xi[s] = 0; xvr[s] = 0.f; }
            }
        }

        // 4) compute chunk i from buf i%NBUF
        {
            const uint32_t* base = smu + (i & (NBUF - 1)) * BUF_U;
            const uint32_t* Ah = base;
            const uint32_t* Al = base + PLANE_U;
#pragma unroll
            for (int kt = 0; kt < 2; kt++) {
                const int ko = (2 * kh + kt) * 8 + 2 * qc;
                uint32_t ah[2][4], al[2][4];
#pragma unroll
                for (int mt = 0; mt < 2; mt++) {
                    const int ra = (RM + mt * 16 + qr) * RSU + ko;
                    const int rb = ra + 8 * RSU;
                    uint2 uh = *(const uint2*)(Ah + ra);
                    uint2 vh = *(const uint2*)(Ah + rb);
                    uint2 ul = *(const uint2*)(Al + ra);
                    uint2 vl = *(const uint2*)(Al + rb);
                    ah[mt][0] = uh.x; ah[mt][1] = vh.x; ah[mt][2] = uh.y; ah[mt][3] = vh.y;
                    al[mt][0] = ul.x; al[mt][1] = vl.x; al[mt][2] = ul.y; al[mt][3] = vl.y;
                }
#pragma unroll
                for (int nt = 0; nt < 4; nt++) {
                    const uint32_t bh[2] = { bhf[kt][nt].x, bhf[kt][nt].y };
                    mma16(acc[0][nt], ah[0], bh);
                    mma16(acc[1][nt], ah[1], bh);
                }
#pragma unroll
                for (int nt = 0; nt < 4; nt++) {
                    const uint32_t bl[2] = { blf[kt][nt].x, blf[kt][nt].y };
                    mma16(acc[0][nt], ah[0], bl);
                    mma16(acc[1][nt], ah[1], bl);
                }
#pragma unroll
                for (int nt = 0; nt < 4; nt++) {
                    const uint32_t bh[2] = { bhf[kt][nt].x, bhf[kt][nt].y };
                    mma16(acc[0][nt], al[0], bh);
                    mma16(acc[1][nt], al[1], bh);
                }
            }
        }
        // barrier every 2 iterations (covers RAW at +2 and WAR at -2)
        if (i & 1) __syncthreads();
    }

    // ---- epilogue: combine k-half partials, then MLP ----
    float* xs  = sm;
    float* l1  = sm + 4224;
    float* l2  = l1 + 1024;
    float* bb1 = l2 + 1024;
    float* bb2 = bb1 + 32;
    float* lw  = bb2 + 32;
    float* lb  = lw + 32;

    for (int i = tid; i < 1024; i += NTHR) { l1[i] = lin1W[i]; l2[i] = lin2W[i]; }
    if (tid < 32) { bb1[tid] = lin1b[tid]; bb2[tid] = lin2b[tid]; lw[tid] = lastW[tid]; }
    if (tid == 0) lb[0] = lastb[0];

    if (kh == 0) {
#pragma unroll
        for (int mt = 0; mt < 2; mt++) {
            const int r0 = RM + mt * 16 + qr;
#pragma unroll
            for (int nt = 0; nt < 4; nt++) {
                const int n = CN + nt * 8 + 2 * qc;
                *(float2*)(xs + r0 * XS_S + n)       = make_float2(acc[mt][nt][0], acc[mt][nt][1]);
                *(float2*)(xs + (r0 + 8) * XS_S + n) = make_float2(acc[mt][nt][2], acc[mt][nt][3]);
            }
        }
    }
    __syncthreads();
    if (kh == 1) {
#pragma unroll
        for (int mt = 0; mt < 2; mt++) {
            const int r0 = RM + mt * 16 + qr;
#pragma unroll
            for (int nt = 0; nt < 4; nt++) {
                const int n = CN + nt * 8 + 2 * qc;
                float2 a = *(float2*)(xs + r0 * XS_S + n);
                float2 b = *(float2*)(xs + (r0 + 8) * XS_S + n);
                a.x += acc[mt][nt][0]; a.y += acc[mt][nt][1];
                b.x += acc[mt][nt][2]; b.y += acc[mt][nt][3];
                *(float2*)(xs + r0 * XS_S + n) = a;
                *(float2*)(xs + (r0 + 8) * XS_S + n) = b;
            }
        }
    }
    __syncthreads();

    if (tid < 2 * MTILE) {
        const int rr = tid >> 1;
        const int half = tid & 1;
        float* xr = xs + rr * XS_S;

        float x[32];
#pragma unroll
        for (int d = 0; d < 32; d++) {
            float s = xr[32 + d];
            x[d] = fmaf(s, s, xr[d]);
        }
        __syncwarp();

        float h[16];
#pragma unroll
        for (int jl = 0; jl < 16; jl++) {
            const int j = half * 16 + jl;
            float a = bb1[j];
            const float* wrow = l1 + j * 32;
#pragma unroll
            for (int d = 0; d < 32; d++) a = fmaf(wrow[d], x[d], a);
            h[jl] = fmaxf(a, 0.0f);
        }
        __syncwarp();
#pragma unroll
        for (int jl = 0; jl < 16; jl++) xr[half * 16 + jl] = h[jl];
        __syncwarp();

        float h1[32];
#pragma unroll
        for (int d = 0; d < 32; d++) h1[d] = xr[d];

        float h2[16];
#pragma unroll
        for (int jl = 0; jl < 16; jl++) {
            const int j = half * 16 + jl;
            float a = bb2[j];
            const float* wrow = l2 + j * 32;
#pragma unroll
            for (int d = 0; d < 32; d++) a = fmaf(wrow[d], h1[d], a);
            h2[jl] = fmaxf(a, 0.0f);
        }
        __syncwarp();
#pragma unroll
        for (int jl = 0; jl < 16; jl++) xr[half * 16 + jl] = h2[jl];
        __syncwarp();

        if (half == 0) {
            const int g = blockIdx.x * MTILE + rr;
            if (g < B) {
                float a = lb[0];
#pragma unroll
                for (int j = 0; j < 32; j++) a = fmaf(lw[j], xr[j], a);
                out[g] = a;
            }
        }
    }
}

extern "C" void kernel_launch(void* const* d_in, const int* in_sizes, int n_in,
                              void* d_out, int out_size)
{
    const int*   Xi      = (const int*)d_in[0];
    const float* Xv      = (const float*)d_in[1];
    const float* emb     = (const float*)d_in[2];
    const float* w_first = (const float*)d_in[3];
    const float* w_inner = (const float*)d_in[4];
    const float* lin1W   = (const float*)d_in[5];
    const float* lin1b   = (const float*)d_in[6];
    const float* lin2W   = (const float*)d_in[7];
    const float* lin2b   = (const float*)d_in[8];
    const float* lastW   = (const float*)d_in[9];
    const float* lastb   = (const float*)d_in[10];
    float* out = (float*)d_out;

    const int B = in_sizes[0] / FDIM;

    prep_b_kernel<<<40, 256>>>(w_first, w_inner);

    cudaFuncSetAttribute(pnn_kernel, cudaFuncAttributeMaxDynamicSharedMemorySize,
                         SMEM_BYTES);
    const int grid = (B + MTILE - 1) / MTILE;
    pnn_kernel<<<grid, NTHR, SMEM_BYTES>>>(Xi, Xv, emb,
                                           lin1W, lin1b, lin2W, lin2b,
                                           lastW, lastb, out, B);
}

// round 13
// speedup vs baseline: 1.0667x; 1.0667x over previous
#include <cuda_runtime.h>
#include <cstdint>

// PNN_62156766707845 — GB300 sm_103a, round 13
// R12 + interleaved (h,l) A layout w/ bank swizzle (STS.64 / LDS.128),
// uint4-packed B fragments. Pipeline: Xi@i+4, emb@i+3, store@i+2, compute@i.

#define FDIM   39
#define EDIM   16
#define VDIM   100000
#define MTILE  64
#define NTHR   256
#define NCHUNK 10
#define FPC    4
#define NBUF   4

#define RSU     80                   // A row stride in u32 (320B), 64 data + 16 pad
#define BUF_U   (64 * RSU)           // 5120 u32 = 20KB per buffer
#define SMEM_BYTES (NBUF * BUF_U * 4)   // 80KB
#define XS_S    66

// B fragments packed: [chunk][ktg][ngroup][lane] = {h0, h1, l0, l1}
__device__ uint4 Bfrag4[NCHUNK][FPC][8][32];

__device__ __forceinline__ uint32_t packbf(float lo, float hi) {
    uint32_t r;
    asm("cvt.rn.bf16x2.f32 %0, %1, %2;" : "=r"(r) : "f"(hi), "f"(lo));
    return r;
}
__device__ __forceinline__ float f_lo(uint32_t u) { return __uint_as_float(u << 16); }
__device__ __forceinline__ float f_hi(uint32_t u) { return __uint_as_float(u & 0xFFFF0000u); }

__device__ __forceinline__ void mma16(float* c, const uint32_t* a, const uint32_t* b) {
    asm volatile(
        "mma.sync.aligned.m16n8k16.row.col.f32.bf16.bf16.f32 "
        "{%0,%1,%2,%3}, {%4,%5,%6,%7}, {%8,%9}, {%0,%1,%2,%3};"
        : "+f"(c[0]), "+f"(c[1]), "+f"(c[2]), "+f"(c[3])
        : "r"(a[0]), "r"(a[1]), "r"(a[2]), "r"(a[3]), "r"(b[0]), "r"(b[1]));
}

// row swizzle: breaks stride-80 bank-parity repetition (units: u32)
__device__ __forceinline__ int rsz(int r) { return ((r >> 1) & 1) * 4; }

// Interleaved store: feature's 4 floats (k=4q..4q+3) -> 2x STS.64 of (h,l)
__device__ __forceinline__ void cvt4_store_i(uint32_t* rowp,
                                             float x0, float x1, float x2, float x3,
                                             int posA) {
    uint32_t h0 = packbf(x0, x1);
    uint32_t h1 = packbf(x2, x3);
    uint32_t l0 = packbf(x0 - f_lo(h0), x1 - f_hi(h0));
    uint32_t l1 = packbf(x2 - f_lo(h1), x3 - f_hi(h1));
    *(uint2*)(rowp + 2 * posA)     = make_uint2(h0, l0);
    *(uint2*)(rowp + 2 * posA + 4) = make_uint2(h1, l1);
}

// ---- B prep kernel: pack {h0,h1,l0,l1} ----
extern "C" __global__ void prep_b_kernel(const float* __restrict__ w_first,
                                         const float* __restrict__ w_inner)
{
    int t = blockIdx.x * blockDim.x + threadIdx.x;
    if (t >= NCHUNK * FPC * 8 * 32) return;
    const int lane = t & 31;
    const int qr = lane >> 2, qc = lane & 3;
    const int ng  = (t >> 5) & 7;
    const int ktg = (t >> 8) & 3;
    const int c   = t >> 10;
    const int n = ng * 8 + qr;
    const int f = c * FPC + ktg;
    float v0 = 0.f, v1 = 0.f, v2 = 0.f, v3 = 0.f;
    if (f < FDIM) {
        const float* src = (n < 32)
            ? (w_first + ((long long)n * FDIM + f) * EDIM)
            : (w_inner + ((long long)(n - 32) * FDIM + f) * EDIM);
        v0 = src[2 * qc];     v1 = src[2 * qc + 1];
        v2 = src[2 * qc + 8]; v3 = src[2 * qc + 9];
    }
    uint32_t h0 = packbf(v0, v1), h1 = packbf(v2, v3);
    uint32_t l0 = packbf(v0 - f_lo(h0), v1 - f_hi(h0));
    uint32_t l1 = packbf(v2 - f_lo(h1), v3 - f_hi(h1));
    Bfrag4[c][ktg][ng][lane] = make_uint4(h0, h1, l0, l1);
}

extern "C" __global__ void __launch_bounds__(NTHR, 2)
pnn_kernel(const int* __restrict__ Xi, const float* __restrict__ Xv,
           const float* __restrict__ emb,
           const float* __restrict__ lin1W, const float* __restrict__ lin1b,
           const float* __restrict__ lin2W, const float* __restrict__ lin2b,
           const float* __restrict__ lastW, const float* __restrict__ lastb,
           float* __restrict__ out, int B)
{
    extern __shared__ float sm[];
    uint32_t* smu = (uint32_t*)sm;

    const int tid  = threadIdx.x;
    const int wid  = tid >> 5;
    const int lane = tid & 31;
    const int qr   = lane >> 2;
    const int qc   = lane & 3;
    const int tq   = wid & 3;
    const int kh   = wid >> 2;
    const int RM   = (tq & 1) * 32;
    const int CN   = (tq >> 1) * 32;
    const int NG0  = CN >> 3;

    // A staging role: thread = (row 0..63, quarter 0..3)
    const int row  = tid >> 2;
    const int q    = tid & 3;
    const int posA = (q < 2) ? 4 * q : 4 * q - 7;
    const int rowoff = row * RSU + rsz(row);
    const int grow = blockIdx.x * MTILE + row;
    const long long rowbase = (long long)((grow < B) ? grow : 0) * FDIM;

    float pf[FPC][4]; float pxv[FPC];
    int   xi[FPC];    float xvr[FPC];

    // ---- prologue: stage chunks 0,1; emb chunk 2 -> pf; Xi chunk 3 -> xi ----
#pragma unroll
    for (int s = 0; s < FPC; s++) {
        int idx = Xi[rowbase + s];
        float xv = Xv[rowbase + s];
        float4 v = *((const float4*)emb + ((long long)s * VDIM + idx) * 4 + q);
        cvt4_store_i(smu + rowoff + s * 16,
                     v.x * xv, v.y * xv, v.z * xv, v.w * xv, posA);

        const int f1 = FPC + s;
        idx = Xi[rowbase + f1];
        xv  = Xv[rowbase + f1];
        v = *((const float4*)emb + ((long long)f1 * VDIM + idx) * 4 + q);
        cvt4_store_i(smu + BUF_U + rowoff + s * 16,
                     v.x * xv, v.y * xv, v.z * xv, v.w * xv, posA);

        const int f2 = 2 * FPC + s;
        idx = Xi[rowbase + f2];
        pxv[s] = Xv[rowbase + f2];
        v = *((const float4*)emb + ((long long)f2 * VDIM + idx) * 4 + q);
        pf[s][0] = v.x; pf[s][1] = v.y; pf[s][2] = v.z; pf[s][3] = v.w;

        const int f3 = 3 * FPC + s;
        xi[s]  = Xi[rowbase + f3];
        xvr[s] = Xv[rowbase + f3];
    }
    __syncthreads();

    float acc[2][4][4];
#pragma unroll
    for (int mt = 0; mt < 2; mt++)
#pragma unroll
        for (int nt = 0; nt < 4; nt++)
#pragma unroll
            for (int c = 0; c < 4; c++) acc[mt][nt][c] = 0.f;

    // precomputed consumer row offsets (u32)
    int raoff[2], rboff[2];
#pragma unroll
    for (int mt = 0; mt < 2; mt++) {
        const int ra = RM + mt * 16 + qr;
        const int rb = ra + 8;
        raoff[mt] = ra * RSU + rsz(ra);
        rboff[mt] = rb * RSU + rsz(rb);
    }

    for (int i = 0; i < NCHUNK; i++) {
        // 0) B fragment LDG.128 for chunk i (L2-resident)
        uint4 bf[2][4];
#pragma unroll
        for (int kt = 0; kt < 2; kt++) {
            const int ktg = 2 * kh + kt;
#pragma unroll
            for (int nt = 0; nt < 4; nt++)
                bf[kt][nt] = Bfrag4[i][ktg][NG0 + nt][lane];
        }
        // 1) cvt+store chunk i+2 from pf into buf (i+2)%NBUF
        if (i + 2 < NCHUNK) {
            uint32_t* base = smu + ((i + 2) & (NBUF - 1)) * BUF_U + rowoff;
#pragma unroll
            for (int s = 0; s < FPC; s++)
                cvt4_store_i(base + s * 16,
                             pf[s][0] * pxv[s], pf[s][1] * pxv[s],
                             pf[s][2] * pxv[s], pf[s][3] * pxv[s], posA);
        }
        // 2) emb LDG chunk i+3 using resident indices
        if (i + 3 < NCHUNK) {
#pragma unroll
            for (int s = 0; s < FPC; s++) {
                const int f = FPC * (i + 3) + s;
                if (f < FDIM) {
                    pxv[s] = xvr[s];
                    float4 v = *((const float4*)emb + ((long long)f * VDIM + xi[s]) * 4 + q);
                    pf[s][0] = v.x; pf[s][1] = v.y; pf[s][2] = v.z; pf[s][3] = v.w;
                } else {
                    pxv[s] = 0.f;
                    pf[s][0] = pf[s][1] = pf[s][2] = pf[s][3] = 0.f;
                }
            }
        }
        // 3) Xi/Xv chunk i+4
        if (i + 4 < NCHUNK) {
#pragma unroll
            for (int s = 0; s < FPC; s++) {
                const int f = FPC * (i + 4) + s;
                if (f < FDIM) {
                    xi[s]  = Xi[rowbase + f];
                    xvr[s] = Xv[rowbase + f];
                } else { xi[s] = 0; xvr[s] = 0.f; }
            }
        }

        // 4) compute chunk i from buf i%NBUF
        {
            const uint32_t* base = smu + (i & (NBUF - 1)) * BUF_U;
#pragma unroll
            for (int kt = 0; kt < 2; kt++) {
                const int ktg = 2 * kh + kt;
                const int co = ktg * 16 + 4 * qc;   // u32 offset within row
                uint32_t ah[2][4], al[2][4];
#pragma unroll
                for (int mt = 0; mt < 2; mt++) {
                    uint4 ua = *(const uint4*)(base + raoff[mt] + co);
                    uint4 ub = *(const uint4*)(base + rboff[mt] + co);
                    ah[mt][0] = ua.x; ah[mt][1] = ub.x; ah[mt][2] = ua.z; ah[mt][3] = ub.z;
                    al[mt][0] = ua.y; al[mt][1] = ub.y; al[mt][2] = ua.w; al[mt][3] = ub.w;
                }
#pragma unroll
                for (int nt = 0; nt < 4; nt++) {
                    const uint32_t bh[2] = { bf[kt][nt].x, bf[kt][nt].y };
                    mma16(acc[0][nt], ah[0], bh);
                    mma16(acc[1][nt], ah[1], bh);
                }
#pragma unroll
                for (int nt = 0; nt < 4; nt++) {
                    const uint32_t bl[2] = { bf[kt][nt].z, bf[kt][nt].w };
                    mma16(acc[0][nt], ah[0], bl);
                    mma16(acc[1][nt], ah[1], bl);
                }
#pragma unroll
                for (int nt = 0; nt < 4; nt++) {
                    const uint32_t bh[2] = { bf[kt][nt].x, bf[kt][nt].y };
                    mma16(acc[0][nt], al[0], bh);
                    mma16(acc[1][nt], al[1], bh);
                }
            }
        }
        // barrier every 2 iterations (covers RAW at +2 and WAR at -2)
        if (i & 1) __syncthreads();
    }

    // ---- epilogue: combine k-half partials, then MLP ----
    float* xs  = sm;
    float* l1  = sm + 4224;
    float* l2  = l1 + 1024;
    float* bb1 = l2 + 1024;
    float* bb2 = bb1 + 32;
    float* lw  = bb2 + 32;
    float* lb  = lw + 32;

    for (int i = tid; i < 1024; i += NTHR) { l1[i] = lin1W[i]; l2[i] = lin2W[i]; }
    if (tid < 32) { bb1[tid] = lin1b[tid]; bb2[tid] = lin2b[tid]; lw[tid] = lastW[tid]; }
    if (tid == 0) lb[0] = lastb[0];

    if (kh == 0) {
#pragma unroll
        for (int mt = 0; mt < 2; mt++) {
            const int r0 = RM + mt * 16 + qr;
#pragma unroll
            for (int nt = 0; nt < 4; nt++) {
                const int n = CN + nt * 8 + 2 * qc;
                *(float2*)(xs + r0 * XS_S + n)       = make_float2(acc[mt][nt][0], acc[mt][nt][1]);
                *(float2*)(xs + (r0 + 8) * XS_S + n) = make_float2(acc[mt][nt][2], acc[mt][nt][3]);
            }
        }
    }
    __syncthreads();
    if (kh == 1) {
#pragma unroll
        for (int mt = 0; mt < 2; mt++) {
            const int r0 = RM + mt * 16 + qr;
#pragma unroll
            for (int nt = 0; nt < 4; nt++) {
                const int n = CN + nt * 8 + 2 * qc;
                float2 a = *(float2*)(xs + r0 * XS_S + n);
                float2 b = *(float2*)(xs + (r0 + 8) * XS_S + n);
                a.x += acc[mt][nt][0]; a.y += acc[mt][nt][1];
                b.x += acc[mt][nt][2]; b.y += acc[mt][nt][3];
                *(float2*)(xs + r0 * XS_S + n) = a;
                *(float2*)(xs + (r0 + 8) * XS_S + n) = b;
            }
        }
    }
    __syncthreads();

    if (tid < 2 * MTILE) {
        const int rr = tid >> 1;
        const int half = tid & 1;
        float* xr = xs + rr * XS_S;

        float x[32];
#pragma unroll
        for (int d = 0; d < 32; d++) {
            float s = xr[32 + d];
            x[d] = fmaf(s, s, xr[d]);
        }
        __syncwarp();

        float h[16];
#pragma unroll
        for (int jl = 0; jl < 16; jl++) {
            const int j = half * 16 + jl;
            float a = bb1[j];
            const float* wrow = l1 + j * 32;
#pragma unroll
            for (int d = 0; d < 32; d++) a = fmaf(wrow[d], x[d], a);
            h[jl] = fmaxf(a, 0.0f);
        }
        __syncwarp();
#pragma unroll
        for (int jl = 0; jl < 16; jl++) xr[half * 16 + jl] = h[jl];
        __syncwarp();

        float h1[32];
#pragma unroll
        for (int d = 0; d < 32; d++) h1[d] = xr[d];

        float h2[16];
#pragma unroll
        for (int jl = 0; jl < 16; jl++) {
            const int j = half * 16 + jl;
            float a = bb2[j];
            const float* wrow = l2 + j * 32;
#pragma unroll
            for (int d = 0; d < 32; d++) a = fmaf(wrow[d], h1[d], a);
            h2[jl] = fmaxf(a, 0.0f);
        }
        __syncwarp();
#pragma unroll
        for (int jl = 0; jl < 16; jl++) xr[half * 16 + jl] = h2[jl];
        __syncwarp();

        if (half == 0) {
            const int g = blockIdx.x * MTILE + rr;
            if (g < B) {
                float a = lb[0];
#pragma unroll
                for (int j = 0; j < 32; j++) a = fmaf(lw[j], xr[j], a);
                out[g] = a;
            }
        }
    }
}

extern "C" void kernel_launch(void* const* d_in, const int* in_sizes, int n_in,
                              void* d_out, int out_size)
{
    const int*   Xi      = (const int*)d_in[0];
    const float* Xv      = (const float*)d_in[1];
    const float* emb     = (const float*)d_in[2];
    const float* w_first = (const float*)d_in[3];
    const float* w_inner = (const float*)d_in[4];
    const float* lin1W   = (const float*)d_in[5];
    const float* lin1b   = (const float*)d_in[6];
    const float* lin2W   = (const float*)d_in[7];
    const float* lin2b   = (const float*)d_in[8];
    const float* lastW   = (const float*)d_in[9];
    const float* lastb   = (const float*)d_in[10];
    float* out = (float*)d_out;

    const int B = in_sizes[0] / FDIM;

    prep_b_kernel<<<40, 256>>>(w_first, w_inner);

    cudaFuncSetAttribute(pnn_kernel, cudaFuncAttributeMaxDynamicSharedMemorySize,
                         SMEM_BYTES);
    const int grid = (B + MTILE - 1) / MTILE;
    pnn_kernel<<<grid, NTHR, SMEM_BYTES>>>(Xi, Xv, emb,
                                           lin1W, lin1b, lin2W, lin2b,
                                           lastW, lastb, out, B);
}